// round 1
// baseline (speedup 1.0000x reference)
#include <cuda_runtime.h>
#include <cstdint>

// RRSVM rank-weighted pooling, 3x3 window, stride 2, pad 1.
// x: [32, 64, 112, 112] f32   s: [64, 3, 3] f32
// outputs (concatenated in d_out as f32):
//   out   [32, 64, 56, 56]          (weighted sum of descending-sorted window)
//   order [32, 64, 56, 56, 9]       (stable argsort indices, stored as float)

#define BB 32
#define CC 64
#define HH 112
#define WW 112
#define HO 56
#define WO 56

// Monotone key: high 32 bits = order-preserving transform of float bits,
// low 4 bits = (15 - k) so that among equal values the SMALLER original
// index k sorts FIRST in descending order (matches stable argsort of -v).
__device__ __forceinline__ unsigned long long make_key(float v, int k) {
    unsigned u = __float_as_uint(v);
    unsigned ord = u ^ (((unsigned)((int)u >> 31)) | 0x80000000u);
    return ((unsigned long long)ord << 4) | (unsigned)(15 - k);
}

__device__ __forceinline__ float key_to_val(unsigned long long key) {
    unsigned ord = (unsigned)(key >> 4);
    unsigned u = (ord & 0x80000000u) ? (ord ^ 0x80000000u) : ~ord;
    return __uint_as_float(u);
}

__global__ void rrsvm_kernel(const float* __restrict__ x,
                             const float* __restrict__ s,
                             float* __restrict__ out,
                             float* __restrict__ order,
                             int write_order) {
    const long long NPIX = (long long)BB * CC * HO * WO;
    long long p = (long long)blockIdx.x * blockDim.x + threadIdx.x;
    if (p >= NPIX) return;

    int wo = (int)(p % WO);
    int ho = (int)((p / WO) % HO);
    int c  = (int)((p / (WO * HO)) % CC);
    int b  = (int)(p / ((long long)WO * HO * CC));

    const float* xp = x + ((long long)(b * CC + c)) * HH * WW;
    int h0 = 2 * ho - 1;
    int w0 = 2 * wo - 1;

    unsigned long long key[9];
    #pragma unroll
    for (int i = 0; i < 3; i++) {
        int h = h0 + i;
        bool hv = ((unsigned)h < (unsigned)HH);
        const float* row = xp + (long long)h * WW;
        #pragma unroll
        for (int j = 0; j < 3; j++) {
            int w = w0 + j;
            float v = (hv && (unsigned)w < (unsigned)WW) ? __ldg(row + w) : 0.0f;
            key[i * 3 + j] = make_key(v, i * 3 + j);
        }
    }

    // Descending compare-exchange: key[i] <- max, key[j] <- min.
    #define CE(i, j) { unsigned long long A = key[i], Bv = key[j]; \
                       bool sw = Bv > A; \
                       key[i] = sw ? Bv : A; key[j] = sw ? A : Bv; }
    // Optimal 25-CE network for n=9.
    CE(0,3) CE(1,7) CE(2,5) CE(4,8)
    CE(0,7) CE(2,4) CE(3,8) CE(5,6)
    CE(0,2) CE(1,3) CE(4,5) CE(7,8)
    CE(1,4) CE(3,6) CE(5,7)
    CE(0,1) CE(2,4) CE(3,5) CE(6,8)
    CE(2,3) CE(4,5) CE(6,7)
    CE(1,2) CE(3,4) CE(5,6)
    #undef CE

    const float* sc = s + c * 9;
    float sum = 0.0f;
    #pragma unroll
    for (int k = 0; k < 9; k++) {
        sum += key_to_val(key[k]) * __ldg(sc + k);
    }
    out[p] = sum;

    if (write_order) {
        float* op = order + p * 9LL;
        #pragma unroll
        for (int k = 0; k < 9; k++) {
            op[k] = (float)(15 - (int)(key[k] & 0xFULL));
        }
    }
}

extern "C" void kernel_launch(void* const* d_in, const int* in_sizes, int n_in,
                              void* d_out, int out_size) {
    const float* x = (const float*)d_in[0];
    const float* s = (const float*)d_in[1];
    const long long NPIX = (long long)BB * CC * HO * WO;  // 6,422,528

    float* out = (float*)d_out;
    float* order = out + NPIX;
    // If out_size covers both tuple members (NPIX * 10 f32 elements), write
    // the order tensor too; otherwise only the weighted-sum output.
    int write_order = ((long long)out_size >= NPIX * 10LL) ? 1 : 0;

    const int threads = 256;
    long long blocks = (NPIX + threads - 1) / threads;
    rrsvm_kernel<<<(unsigned)blocks, threads>>>(x, s, out, order, write_order);
}

// round 2
// speedup vs baseline: 1.6136x; 1.6136x over previous
#include <cuda_runtime.h>
#include <cstdint>

// RRSVM rank-weighted pooling, 3x3 window, stride 2, pad 1.
// x: [32, 64, 112, 112] f32   s: [64, 3, 3] f32
// d_out (f32, concatenated): out [32,64,56,56], order [32,64,56,56,9]

#define BB 32
#define CC 64
#define HH 112
#define WW 112
#define HO 56
#define WO 56
#define PIX_PER_CH (HO * WO)      // 3136
#define NQ (BB * CC)              // 2048
#define TPB 256

__global__ void __launch_bounds__(TPB) rrsvm_kernel(
        const float* __restrict__ x,
        const float* __restrict__ s,
        float* __restrict__ out,
        float* __restrict__ order,
        int write_order) {
    __shared__ float s_sh[18];          // s rows for the (<=2) channels this block touches
    __shared__ float ord_sh[TPB * 9];   // order staging for coalesced writes

    const int tid = threadIdx.x;
    const long long p0 = (long long)blockIdx.x * TPB;
    const long long p = p0 + tid;

    const int q_first = (int)(p0 / PIX_PER_CH);
    const int q = (int)(p / PIX_PER_CH);

    // Load the 1-2 needed s rows (9 floats each) into shared.
    if (tid < 18) {
        int qq = q_first + tid / 9;
        if (qq < NQ) s_sh[tid] = s[(qq & (CC - 1)) * 9 + (tid % 9)];
    }
    __syncthreads();

    const int cbase = (q - q_first) * 9;   // 0 or 9
    const int pix = (int)(p % PIX_PER_CH);
    const int wo = pix % WO;
    const int ho = pix / WO;

    const float* xp = x + (long long)q * (HH * WW);
    const int h0 = 2 * ho - 1;
    const int w0 = 2 * wo - 1;

    float v[9];
    #pragma unroll
    for (int i = 0; i < 3; i++) {
        int h = h0 + i;
        bool hv = ((unsigned)h < (unsigned)HH);
        const float* row = xp + h * WW;
        #pragma unroll
        for (int j = 0; j < 3; j++) {
            int w = w0 + j;
            v[i * 3 + j] = (hv && (unsigned)w < (unsigned)WW) ? __ldg(row + w) : 0.0f;
        }
    }

    // Pairwise ranks. For pair (i<j): strict v[j] > v[i] puts j first; ties
    // keep index order (matches stable argsort of -patches).
    // Init r[j] = j  (= number of (i<j) pairs), then subtract when j wins.
    int r[9];
    #pragma unroll
    for (int k = 0; k < 9; k++) r[k] = k;
    #pragma unroll
    for (int i = 0; i < 8; i++) {
        #pragma unroll
        for (int j = i + 1; j < 9; j++) {
            int gt = (v[j] > v[i]);
            r[i] += gt;
            r[j] -= gt;
        }
    }

    // Weighted sum: out = sum_k v[k] * s[rank_k]
    float sum = 0.0f;
    #pragma unroll
    for (int k = 0; k < 9; k++) {
        sum += v[k] * s_sh[cbase + r[k]];
    }
    out[p] = sum;

    if (write_order) {
        // Scatter order indices into this thread's 9-word staging segment:
        // segment[rank_k] = k  (as float).
        float* my = ord_sh + tid * 9;
        #pragma unroll
        for (int k = 0; k < 9; k++) {
            my[r[k]] = (float)k;
        }
        __syncwarp();
        // Warp-coalesced copy-out: each warp owns 288 contiguous floats.
        const int w = tid >> 5;
        const int lane = tid & 31;
        const float* src = ord_sh + w * 288;
        float* dst = order + (p0 + (long long)w * 32) * 9;
        #pragma unroll
        for (int k = 0; k < 9; k++) {
            dst[lane + 32 * k] = src[lane + 32 * k];
        }
    }
}

extern "C" void kernel_launch(void* const* d_in, const int* in_sizes, int n_in,
                              void* d_out, int out_size) {
    const float* x = (const float*)d_in[0];
    const float* s = (const float*)d_in[1];
    const long long NPIX = (long long)BB * CC * HO * WO;  // 6,422,528

    float* out = (float*)d_out;
    float* order = out + NPIX;
    int write_order = ((long long)out_size >= NPIX * 10LL) ? 1 : 0;

    const long long blocks = (NPIX + TPB - 1) / TPB;  // 25088, exact
    rrsvm_kernel<<<(unsigned)blocks, TPB>>>(x, s, out, order, write_order);
}